// round 2
// baseline (speedup 1.0000x reference)
#include <cuda_runtime.h>
#include <cstdint>

#define T_DIM 256
#define C_DIM 128
#define L_DIM 48
#define PD    16         // prefetch pipeline depth (rows in flight per warp)

// One warp per batch element. lane handles extended states s = 4*lane + j, j=0..3.
// S = 2*L+1 = 97 states: lanes 0..23 fully valid, lane 24 only j=0 (s=96).
// Linear-space CTC forward, 128x prescale, warp-sum renorm every 8 steps.
// Rows are read COALESCED (LDG.128 per lane), staged in a 2-deep smem ring,
// and per-lane class probs gathered via LDS (blank = broadcast).
__global__ __launch_bounds__(32)
void ctc_fwd_kernel(const float* __restrict__ y,      // [B, T, C] softmax probs
                    const int*   __restrict__ labels, // [B, L]
                    float*       __restrict__ out)    // [B]
{
    __shared__ float ring[2][C_DIM];

    const int b    = blockIdx.x;
    const int lane = threadIdx.x;

    const float4* rowv = (const float4*)(y + (size_t)b * (T_DIM * C_DIM));
    const int*    lb   = labels + (size_t)b * L_DIM;

    // --- per-lane static state: classes + skip masks + validity ---
    const bool lv = (lane < 24);
    int c0 = 127, c1 = 127, cm1 = -1;
    if (lv) { c0 = lb[2 * lane]; c1 = lb[2 * lane + 1]; }
    if (lane >= 1 && lane < 24) cm1 = lb[2 * lane - 1];

    const float m1 = (lane >= 1 && lv && c0 != cm1) ? 1.0f : 0.0f; // skip into s=4l+1
    const float m3 = (lv && c1 != c0)               ? 1.0f : 0.0f; // skip into s=4l+3

    const bool v0 = (lane <= 24);
    const bool v13 = lv;

    const float SC = 128.0f, EB = 1.28e-5f;   // p_scaled = fmaf(p, 128, 128e-7)

    // --- prologue: rows 0..PD-1 in flight ---
    float4 q[PD];
#pragma unroll
    for (int d = 0; d < PD; d++)
        q[d] = rowv[(size_t)d * (C_DIM / 4) + lane];

    // --- step t = 0: init alpha from staged row 0 ---
    ((float4*)ring[0])[lane] = q[0];
    q[0] = rowv[(size_t)PD * (C_DIM / 4) + lane];   // prefetch row 16
    __syncwarp();
    {
        const float pb = ring[0][127];
        const float p0 = ring[0][c0];
        float a = (lane == 0) ? fmaf(pb, SC, EB) : 0.0f;
        float bb = (lane == 0) ? fmaf(p0, SC, EB) : 0.0f;
        // stash into persistent regs below
        // (declared after to keep scope simple)
        // -- handled via variables declared next --
        ring[1][0] = 0.0f; (void)a; (void)bb; // no-op to keep compiler quiet? no—use real init:
    }
    // real alpha registers
    float a0, a1, a2 = 0.0f, a3 = 0.0f;
    {
        const float pb = ring[0][127];
        const float p0 = ring[0][c0];
        a0 = (lane == 0) ? fmaf(pb, SC, EB) : 0.0f;
        a1 = (lane == 0) ? fmaf(p0, SC, EB) : 0.0f;
    }

    float acc = 0.0f;   // accumulated log of normalization constants

    for (int tb = 1; tb < T_DIM; tb += PD) {
#pragma unroll
        for (int d = 0; d < PD; d++) {
            const int t = tb + d;
            if (t < T_DIM) {
                const int slot = (t & (PD - 1));
                float4 r = q[slot];
                float* row = ring[t & 1];
                ((float4*)row)[lane] = r;
                if (t + PD < T_DIM)
                    q[slot] = rowv[(size_t)(t + PD) * (C_DIM / 4) + lane];
                __syncwarp();

                const float pb = row[127];
                const float g0 = row[c0];
                const float g1 = row[c1];

                const float pcb = v0  ? fmaf(pb, SC, EB) : 0.0f;  // blank (s=4l, 4l+2)
                const float pc1 = v13 ? fmaf(g0, SC, EB) : 0.0f;
                const float pc3 = v13 ? fmaf(g1, SC, EB) : 0.0f;
                const float pcb2 = v13 ? fmaf(pb, SC, EB) : 0.0f;

                float up3 = __shfl_up_sync(0xffffffffu, a3, 1);   // alpha[4l-1]
                if (lane == 0) up3 = 0.0f;

                const float n0 = (a0 + up3)             * pcb;    // s=4l
                const float n1 = fmaf(m1, up3, a1 + a0) * pc1;    // s=4l+1
                const float n2 = (a2 + a1)              * pcb2;   // s=4l+2
                const float n3 = fmaf(m3, a1, a3 + a2)  * pc3;    // s=4l+3

                a0 = n0; a1 = n1; a2 = n2; a3 = n3;
            }
            // renormalize every 8 steps (d==7, d==15 since tb ≡ 1 mod 16);
            // linear recurrence => scaling commutes; fold log into acc.
            if (d == 7 || d == PD - 1) {
                float s = (a0 + a1) + (a2 + a3);
#pragma unroll
                for (int o = 16; o; o >>= 1) s += __shfl_xor_sync(0xffffffffu, s, o);
                acc += __logf(s);
                const float inv = __frcp_rn(s);
                a0 *= inv; a1 *= inv; a2 *= inv; a3 *= inv;
            }
        }
    }

    // loss = T*log(128) - acc - log(alpha[95] + alpha[96])
    const float v95 = __shfl_sync(0xffffffffu, a3, 23);  // s = 95
    const float v96 = __shfl_sync(0xffffffffu, a0, 24);  // s = 96
    if (lane == 0) {
        const float offs = 1242.11974756972f;            // 256 * ln(128)
        out[b] = offs - acc - __logf(v95 + v96);
    }
}

extern "C" void kernel_launch(void* const* d_in, const int* in_sizes, int n_in,
                              void* d_out, int out_size)
{
    const float* y      = (const float*)d_in[0];   // [B, T, C] float32
    const int*   labels = (const int*)d_in[1];     // [B, L] int32
    float*       out    = (float*)d_out;           // [B, 1] float32
    const int B = in_sizes[1] / L_DIM;
    ctc_fwd_kernel<<<B, 32>>>(y, labels, out);
}

// round 14
// speedup vs baseline: 3.0300x; 3.0300x over previous
#include <cuda_runtime.h>
#include <cstdint>

#define T_DIM 256
#define C_DIM 128
#define L_DIM 48
#define RING  32        // rows resident in the smem ring (16 KB)
#define BLK   8         // steps per block == rows per cp.async commit group

__device__ __forceinline__ void cp_async16(uint32_t smem, const float* gmem) {
    asm volatile("cp.async.cg.shared.global [%0], [%1], 16;\n"
                 :: "r"(smem), "l"(gmem));
}
__device__ __forceinline__ void cp_commit() {
    asm volatile("cp.async.commit_group;\n" ::: "memory");
}
template <int N>
__device__ __forceinline__ void cp_wait() {
    asm volatile("cp.async.wait_group %0;\n" :: "n"(N) : "memory");
}

// One warp per batch element. lane handles extended states s = 4*lane + j, j=0..3.
// S = 2*48+1 = 97 states: lanes 0..23 fully valid, lane 24 only j=0 (s=96).
// Linear-space CTC forward, 128x prescale, warp-sum renorm every 8 steps.
// Rows stream GMEM->SMEM via cp.async (coalesced 512B rows, 2 groups = 16 rows
// in flight); per-lane class probs gathered via LDS (blank col = broadcast).
__global__ __launch_bounds__(32)
void ctc_fwd_kernel(const float* __restrict__ y,      // [B, T, C] softmax probs
                    const int*   __restrict__ labels, // [B, L]
                    float*       __restrict__ out)    // [B]
{
    __shared__ float ring[RING][C_DIM];               // 16 KB

    const int b    = blockIdx.x;
    const int lane = threadIdx.x;

    const float* yb = y + (size_t)b * (T_DIM * C_DIM);
    const int*   lb = labels + (size_t)b * L_DIM;
    const uint32_t rb = (uint32_t)__cvta_generic_to_shared(&ring[0][0]);

    // --- per-lane static state: classes + skip masks + validity ---
    const bool lv = (lane < 24);
    int c0 = 127, c1 = 127, cm1 = -1;
    if (lv) { c0 = lb[2 * lane]; c1 = lb[2 * lane + 1]; }
    if (lane >= 1 && lane < 24) cm1 = lb[2 * lane - 1];

    const float m1 = (lane >= 1 && lv && c0 != cm1) ? 1.0f : 0.0f; // skip into s=4l+1
    const float m3 = (lv && c1 != c0)               ? 1.0f : 0.0f; // skip into s=4l+3
    const bool  v0  = (lane <= 24);
    const bool  v13 = lv;

    const float SC = 128.0f, EB = 1.28e-5f;   // p_scaled = fmaf(p, 128, 128e-7)

    // --- prologue: rows 0..7 (group) and 8..15 (group) ---
#pragma unroll
    for (int r = 0; r < 8; r++)
        cp_async16(rb + (uint32_t)(r * 512 + lane * 16), yb + r * C_DIM + lane * 4);
    cp_commit();
#pragma unroll
    for (int r = 8; r < 16; r++)
        cp_async16(rb + (uint32_t)(r * 512 + lane * 16), yb + r * C_DIM + lane * 4);
    cp_commit();

    float a0 = 0.0f, a1 = 0.0f, a2 = 0.0f, a3 = 0.0f;
    float acc = 0.0f;                                 // sum of log normalizers

    for (int tb = 0; tb < T_DIM; tb += BLK) {
        // issue rows tb+16 .. tb+23 as one group (empty group at tail keeps
        // the pending-group count aligned; groups retire in commit order)
        const int qrow = tb + 2 * BLK;
        if (qrow < T_DIM) {
            const uint32_t dst = rb + (uint32_t)(((qrow & (RING - 1)) * 512) + lane * 16);
            const float*   src = yb + (size_t)qrow * C_DIM + lane * 4;
#pragma unroll
            for (int r = 0; r < 8; r++)
                cp_async16(dst + (uint32_t)(r * 512), src + r * C_DIM);
        }
        cp_commit();
        cp_wait<2>();          // all but newest 2 groups done => rows tb..tb+7 ready
        __syncwarp();

        const float* rows = &ring[tb & (RING - 1)][0];
#pragma unroll
        for (int d = 0; d < BLK; d++) {
            const float* row = rows + d * C_DIM;
            const float pb = row[127];
            const float g0 = row[c0];
            const float g1 = row[c1];

            const float pcb  = v0  ? fmaf(pb, SC, EB) : 0.0f;  // blank, s=4l
            const float pcb2 = v13 ? fmaf(pb, SC, EB) : 0.0f;  // blank, s=4l+2
            const float pc1  = v13 ? fmaf(g0, SC, EB) : 0.0f;
            const float pc3  = v13 ? fmaf(g1, SC, EB) : 0.0f;

            if (tb == 0 && d == 0) {
                // t = 0 init: alpha[0] = p(blank), alpha[1] = p(label0)
                a0 = (lane == 0) ? pcb : 0.0f;
                a1 = (lane == 0) ? pc1 : 0.0f;
            } else {
                float up3 = __shfl_up_sync(0xffffffffu, a3, 1);   // alpha[4l-1]
                if (lane == 0) up3 = 0.0f;
                const float n0 = (a0 + up3)             * pcb;    // s=4l
                const float n1 = fmaf(m1, up3, a1 + a0) * pc1;    // s=4l+1
                const float n2 = (a2 + a1)              * pcb2;   // s=4l+2
                const float n3 = fmaf(m3, a1, a3 + a2)  * pc3;    // s=4l+3
                a0 = n0; a1 = n1; a2 = n2; a3 = n3;
            }
        }

        // renormalize (linear recurrence => scaling commutes; fold into acc)
        float s = (a0 + a1) + (a2 + a3);
#pragma unroll
        for (int o = 16; o; o >>= 1) s += __shfl_xor_sync(0xffffffffu, s, o);
        acc += __logf(s);
        const float inv = __frcp_rn(s);
        a0 *= inv; a1 *= inv; a2 *= inv; a3 *= inv;
    }

    // loss = T*log(128) - acc - log(alpha[95] + alpha[96])
    const float v95 = __shfl_sync(0xffffffffu, a3, 23);  // s = 95
    const float v96 = __shfl_sync(0xffffffffu, a0, 24);  // s = 96
    if (lane == 0) {
        const float offs = 1242.11974756972f;            // 256 * ln(128)
        out[b] = offs - acc - __logf(v95 + v96);
    }
}

extern "C" void kernel_launch(void* const* d_in, const int* in_sizes, int n_in,
                              void* d_out, int out_size)
{
    const float* y      = (const float*)d_in[0];   // [B, T, C] float32
    const int*   labels = (const int*)d_in[1];     // [B, L] int32
    float*       out    = (float*)d_out;           // [B, 1] float32
    const int B = in_sizes[1] / L_DIM;
    ctc_fwd_kernel<<<B, 32>>>(y, labels, out);
}

// round 15
// speedup vs baseline: 4.1761x; 1.3782x over previous
#include <cuda_runtime.h>
#include <cstdint>

#define T_DIM 256
#define C_DIM 128
#define L_DIM 48
#define STAGES 6            // ring stages (8 rows x 512B each = 4KB/stage, 24KB)
#define BLK    8            // rows (time steps) per stage
#define NBLK   (T_DIM / BLK)   // 32 blocks
#define AHEAD  5            // stages issued ahead of consumption

// One warp per batch element. lane handles extended states s = 4*lane + j.
// S = 2*48+1 = 97: lanes 0..23 fully valid, lane 24 only j=0 (s=96).
// Linear-space CTC forward, 128x prescale, exact power-of-2 renorm per 8 steps.
// Rows stream GMEM->SMEM via cp.async.bulk (TMA) + mbarrier, 5 stages in flight.
__global__ __launch_bounds__(32)
void ctc_fwd_kernel(const float* __restrict__ y,      // [B, T, C] softmax probs
                    const int*   __restrict__ labels, // [B, L]
                    float*       __restrict__ out)    // [B]
{
    __shared__ alignas(1024) float ring[STAGES][BLK][C_DIM];  // 24 KB
    __shared__ alignas(8) uint64_t mbar[STAGES];

    const int b    = blockIdx.x;
    const int lane = threadIdx.x;

    const float* yb = y + (size_t)b * (T_DIM * C_DIM);
    const int*   lb = labels + (size_t)b * L_DIM;

    const uint32_t ring_s = (uint32_t)__cvta_generic_to_shared(&ring[0][0][0]);
    const uint32_t mbar_s = (uint32_t)__cvta_generic_to_shared(&mbar[0]);

    // --- init mbarriers (count = 1; completion via expect_tx) ---
    if (lane == 0) {
#pragma unroll
        for (int s = 0; s < STAGES; s++)
            asm volatile("mbarrier.init.shared.b64 [%0], %1;"
                         :: "r"(mbar_s + s * 8), "r"(1) : "memory");
    }
    __syncwarp();

    // --- prologue: issue stages 0..AHEAD-1 ---
    if (lane == 0) {
#pragma unroll
        for (int k = 0; k < AHEAD; k++) {
            asm volatile("mbarrier.arrive.expect_tx.shared.b64 _, [%0], %1;"
                         :: "r"(mbar_s + k * 8), "r"(BLK * C_DIM * 4) : "memory");
            asm volatile(
                "cp.async.bulk.shared::cluster.global.mbarrier::complete_tx::bytes "
                "[%0], [%1], %2, [%3];"
                :: "r"(ring_s + k * (BLK * C_DIM * 4)),
                   "l"(yb + (size_t)k * BLK * C_DIM),
                   "r"(BLK * C_DIM * 4),
                   "r"(mbar_s + k * 8) : "memory");
        }
    }

    // --- per-lane static state: classes + skip masks + validity ---
    const bool lv = (lane < 24);
    int c0 = 127, c1 = 127, cm1 = -1;
    if (lv) { c0 = lb[2 * lane]; c1 = lb[2 * lane + 1]; }
    if (lane >= 1 && lane < 24) cm1 = lb[2 * lane - 1];

    const float m1 = (lane >= 1 && lv && c0 != cm1) ? 1.0f : 0.0f; // skip into s=4l+1
    const float m3 = (lv && c1 != c0)               ? 1.0f : 0.0f; // skip into s=4l+3
    const bool  v0  = (lane <= 24);
    const bool  v13 = lv;

    const float SC = 128.0f, EB = 1.28e-5f;   // p_scaled = fmaf(p, 128, 128e-7)

    float a0 = 0.0f, a1 = 0.0f, a2 = 0.0f, a3 = 0.0f;
    int acc_e = 0;                            // accumulated base-2 exponent

    for (int k = 0; k < NBLK; k++) {
        const int st = k % STAGES;
        const uint32_t par = (uint32_t)((k / STAGES) & 1);

        // wait for stage k (acquire)
        {
            uint32_t mb = mbar_s + st * 8;
            uint32_t done;
            asm volatile(
                "{\n\t.reg .pred p;\n\t"
                "mbarrier.try_wait.parity.acquire.cta.shared::cta.b64 p, [%1], %2;\n\t"
                "selp.b32 %0, 1, 0, p;\n\t}"
                : "=r"(done) : "r"(mb), "r"(par) : "memory");
            if (!done) {
                asm volatile(
                    "{\n\t.reg .pred P1;\n\t"
                    "W_%=:\n\t"
                    "mbarrier.try_wait.parity.acquire.cta.shared::cta.b64 P1, [%0], %1, 0x989680;\n\t"
                    "@P1 bra.uni D_%=;\n\t"
                    "bra.uni W_%=;\n\t"
                    "D_%=:\n\t}"
                    :: "r"(mb), "r"(par) : "memory");
            }
        }

        const float* rows = &ring[st][0][0];
#pragma unroll
        for (int d = 0; d < BLK; d++) {
            const float* row = rows + d * C_DIM;
            const float pb = row[127];
            const float g0 = row[c0];
            const float g1 = row[c1];

            const float pcb  = v0  ? fmaf(pb, SC, EB) : 0.0f;  // blank, s=4l
            const float pcb2 = v13 ? fmaf(pb, SC, EB) : 0.0f;  // blank, s=4l+2
            const float pc1  = v13 ? fmaf(g0, SC, EB) : 0.0f;
            const float pc3  = v13 ? fmaf(g1, SC, EB) : 0.0f;

            if (k == 0 && d == 0) {
                // t = 0 init: alpha[0] = p(blank), alpha[1] = p(label0)
                a0 = (lane == 0) ? pcb : 0.0f;
                a1 = (lane == 0) ? pc1 : 0.0f;
            } else {
                float up3 = __shfl_up_sync(0xffffffffu, a3, 1);   // alpha[4l-1]
                if (lane == 0) up3 = 0.0f;
                const float n0 = (a0 + up3)             * pcb;    // s=4l
                const float n1 = fmaf(m1, up3, a1 + a0) * pc1;    // s=4l+1
                const float n2 = (a2 + a1)              * pcb2;   // s=4l+2
                const float n3 = fmaf(m3, a1, a3 + a2)  * pc3;    // s=4l+3
                a0 = n0; a1 = n1; a2 = n2; a3 = n3;
            }
        }

        // exact power-of-2 renorm (scaling commutes through linear recurrence)
        float sum = (a0 + a1) + (a2 + a3);
#pragma unroll
        for (int o = 16; o; o >>= 1) sum += __shfl_xor_sync(0xffffffffu, sum, o);
        const int e = (__float_as_int(sum) >> 23) & 0xff;        // biased exponent
        const float inv = __int_as_float((254 - e) << 23);        // 2^(127-e)
        acc_e += e - 127;
        a0 *= inv; a1 *= inv; a2 *= inv; a3 *= inv;

        __syncwarp();

        // issue stage k+AHEAD (overwrites stage consumed at block k-1)
        const int kn = k + AHEAD;
        if (kn < NBLK && lane == 0) {
            const int sn = kn % STAGES;
            asm volatile("fence.proxy.async.shared::cta;" ::: "memory");
            asm volatile("mbarrier.arrive.expect_tx.shared.b64 _, [%0], %1;"
                         :: "r"(mbar_s + sn * 8), "r"(BLK * C_DIM * 4) : "memory");
            asm volatile(
                "cp.async.bulk.shared::cluster.global.mbarrier::complete_tx::bytes "
                "[%0], [%1], %2, [%3];"
                :: "r"(ring_s + sn * (BLK * C_DIM * 4)),
                   "l"(yb + (size_t)kn * BLK * C_DIM),
                   "r"(BLK * C_DIM * 4),
                   "r"(mbar_s + sn * 8) : "memory");
        }
    }

    // loss = T*log(128) - acc_e*ln2 - log(alpha[95] + alpha[96])
    const float v95 = __shfl_sync(0xffffffffu, a3, 23);  // s = 95
    const float v96 = __shfl_sync(0xffffffffu, a0, 24);  // s = 96
    if (lane == 0) {
        const float offs = 1242.11974756972f;            // 256 * ln(128)
        out[b] = offs - (float)acc_e * 0.69314718056f - __logf(v95 + v96);
    }
}

extern "C" void kernel_launch(void* const* d_in, const int* in_sizes, int n_in,
                              void* d_out, int out_size)
{
    const float* y      = (const float*)d_in[0];   // [B, T, C] float32
    const int*   labels = (const int*)d_in[1];     // [B, L] int32
    float*       out    = (float*)d_out;           // [B, 1] float32
    const int B = in_sizes[1] / L_DIM;
    ctc_fwd_kernel<<<B, 32>>>(y, labels, out);
}